// round 5
// baseline (speedup 1.0000x reference)
#include <cuda_runtime.h>
#include <mma.h>
#include <cstddef>

using namespace nvcuda;

#define N_NODES 50000
#define D 128
#define E_EDGES 800000
#define SCAN_BLK 1024
#define SCAN_NB ((N_NODES + SCAN_BLK - 1) / SCAN_BLK)   // 49
#define FULL_TILES (N_NODES / 128)                       // 390
#define TAIL_ROW0 (FULL_TILES * 128)                     // 49920

// Scratch (no allocations allowed in kernel_launch)
__device__ float d_agg[(size_t)N_NODES * D];   // mean-aggregated features
__device__ float d_h[(size_t)N_NODES * D];     // layer-1 output
__device__ int   d_deg[N_NODES];
__device__ int   d_rowptr[N_NODES + 1];
__device__ int   d_cursor[N_NODES + 1];
__device__ int   d_adj[E_EDGES];               // src ids grouped by dst
__device__ int   d_bsum[64];
__device__ int   d_boff[64];
__device__ float d_wt1[256 * 128];             // combined [Wl1;Wr1] transposed: wt[k][j]
__device__ float d_wt2[256 * 128];

// ---------------------------------------------------------------------------
__global__ void zero_deg_kernel() {
    int i = blockIdx.x * blockDim.x + threadIdx.x;
    if (i < N_NODES) d_deg[i] = 0;
}

__global__ void count_kernel(const int* __restrict__ dst) {
    int stride = gridDim.x * blockDim.x;
    for (int e = blockIdx.x * blockDim.x + threadIdx.x; e < E_EDGES; e += stride) {
        atomicAdd(&d_deg[dst[e]], 1);
    }
}

__global__ void scan1_kernel() {
    __shared__ int sh[SCAN_BLK];
    int i = blockIdx.x * SCAN_BLK + threadIdx.x;
    int v = (i < N_NODES) ? d_deg[i] : 0;
    sh[threadIdx.x] = v;
    __syncthreads();
#pragma unroll
    for (int off = 1; off < SCAN_BLK; off <<= 1) {
        int t = (threadIdx.x >= off) ? sh[threadIdx.x - off] : 0;
        __syncthreads();
        sh[threadIdx.x] += t;
        __syncthreads();
    }
    if (i < N_NODES) d_rowptr[i + 1] = sh[threadIdx.x];
    if (threadIdx.x == SCAN_BLK - 1) d_bsum[blockIdx.x] = sh[threadIdx.x];
}

__global__ void scan2_kernel() {
    __shared__ int sh[64];
    int t = threadIdx.x;
    int v = (t < SCAN_NB) ? d_bsum[t] : 0;
    sh[t] = v;
    __syncthreads();
#pragma unroll
    for (int off = 1; off < 64; off <<= 1) {
        int u = (t >= off) ? sh[t - off] : 0;
        __syncthreads();
        sh[t] += u;
        __syncthreads();
    }
    d_boff[t] = sh[t] - v;   // exclusive
}

__global__ void scan3_kernel() {
    int i = blockIdx.x * blockDim.x + threadIdx.x;
    if (i == 0) { d_rowptr[0] = 0; d_cursor[0] = 0; }
    if (i < N_NODES) {
        int r = d_rowptr[i + 1] + d_boff[i >> 10];
        d_rowptr[i + 1] = r;
        d_cursor[i + 1] = r;
    }
}

__global__ void fill_kernel(const int* __restrict__ src, const int* __restrict__ dst) {
    int stride = gridDim.x * blockDim.x;
    for (int e = blockIdx.x * blockDim.x + threadIdx.x; e < E_EDGES; e += stride) {
        int d = dst[e];
        int p = atomicAdd(&d_cursor[d], 1);
        d_adj[p] = src[e];
    }
}

// wt[k*128+j]: k<128 -> Wl[j][k]; k>=128 -> Wr[j][k-128]
__global__ void prep_kernel(const float* __restrict__ Wl1, const float* __restrict__ Wr1,
                            const float* __restrict__ Wl2, const float* __restrict__ Wr2) {
    int stride = gridDim.x * blockDim.x;
    for (int i = blockIdx.x * blockDim.x + threadIdx.x; i < 256 * 128; i += stride) {
        int k = i >> 7;
        int j = i & 127;
        if (k < 128) {
            d_wt1[i] = Wl1[j * 128 + k];
            d_wt2[i] = Wl2[j * 128 + k];
        } else {
            d_wt1[i] = Wr1[j * 128 + (k - 128)];
            d_wt2[i] = Wr2[j * 128 + (k - 128)];
        }
    }
}

// One warp per node: sum neighbor rows, scale by 1/deg, store (2-deep pipeline).
__global__ void __launch_bounds__(256) gather_kernel(const float* __restrict__ x, int layer) {
    const float* __restrict__ xin = (layer == 0) ? x : d_h;
    int gid = blockIdx.x * blockDim.x + threadIdx.x;
    int n = gid >> 5;
    if (n >= N_NODES) return;
    int lane = gid & 31;
    int base = d_rowptr[n];
    int end  = d_rowptr[n + 1];
    int deg  = end - base;

    float4 acc = make_float4(0.f, 0.f, 0.f, 0.f);
    for (int i = base; i < end; i += 32) {
        int cnt = min(32, end - i);
        int sidx = (lane < cnt) ? __ldg(d_adj + i + lane) : 0;
        int s0 = __shfl_sync(0xffffffffu, sidx, 0);
        float4 v = *(const float4*)(xin + (size_t)s0 * D + lane * 4);
        for (int j = 1; j < cnt; j++) {
            int s = __shfl_sync(0xffffffffu, sidx, j);
            float4 vn = *(const float4*)(xin + (size_t)s * D + lane * 4);
            acc.x += v.x; acc.y += v.y; acc.z += v.z; acc.w += v.w;
            v = vn;
        }
        acc.x += v.x; acc.y += v.y; acc.z += v.z; acc.w += v.w;
    }
    float sc = 1.0f / fmaxf((float)deg, 1.0f);
    acc.x *= sc; acc.y *= sc; acc.z *= sc; acc.w *= sc;
    *(float4*)(d_agg + (size_t)n * D + lane * 4) = acc;
}

// ---------------------------------------------------------------------------
// TF32 tensor-core GEMM: out[128 rows/block][128] = [agg|xin] @ wt + bias.
// BM=128, BN=128, BK=16. 8 warps, each 32x64 (2x4 m16n16k8 frags).
// Bias folded in via accumulator init from a broadcast tile. Full tiles only.
__global__ void __launch_bounds__(256) gemm_tf32_kernel(const float* __restrict__ x,
                                                        const float* __restrict__ bias,
                                                        float* __restrict__ outp,
                                                        int layer) {
    const float* __restrict__ wt  = (layer == 0) ? d_wt1 : d_wt2;
    const float* __restrict__ xin = (layer == 0) ? x : d_h;
    float* __restrict__ out       = (layer == 0) ? d_h : outp;

    __shared__ float As[128][16];      // [m][k] row-major, ld=16
    __shared__ float Bs[16][136];      // [k][n] row-major, ld=136
    __shared__ float BiasSh[16][136];  // 16 replicated bias rows

    int tid = threadIdx.x;
    int wid = tid >> 5;
    int warp_m = (wid & 3) * 32;       // 0,32,64,96
    int warp_n = (wid >> 2) * 64;      // 0,64
    int block_row0 = blockIdx.x * 128;

    // fill bias broadcast tile (16 rows x 128)
    for (int i = tid; i < 16 * 128; i += 256) {
        BiasSh[i >> 7][i & 127] = __ldg(bias + (i & 127));
    }
    __syncthreads();

    wmma::fragment<wmma::accumulator, 16, 16, 8, float> c[2][4];
#pragma unroll
    for (int i = 0; i < 2; i++)
#pragma unroll
        for (int j = 0; j < 4; j++)
            wmma::load_matrix_sync(c[i][j], &BiasSh[0][warp_n + j * 16], 136,
                                   wmma::mem_row_major);

    for (int kt = 0; kt < 256; kt += 16) {
        const float* __restrict__ asrc = (kt < 128) ? d_agg : xin;
        int kbase = (kt < 128) ? kt : (kt - 128);
        // load A tile 128x16 (float4 per thread x2)
#pragma unroll
        for (int p = 0; p < 2; p++) {
            int idx = tid + p * 256;          // 0..511
            int r = idx >> 2;
            int kq = (idx & 3) * 4;
            float4 v = *(const float4*)(asrc + (size_t)(block_row0 + r) * D + kbase + kq);
            *(float4*)&As[r][kq] = v;
        }
        // load B tile 16x128
#pragma unroll
        for (int p = 0; p < 2; p++) {
            int idx = tid + p * 256;
            int k = idx >> 5;
            int j = (idx & 31) * 4;
            *(float4*)&Bs[k][j] = *(const float4*)(wt + (size_t)(kt + k) * 128 + j);
        }
        __syncthreads();

#pragma unroll
        for (int kk = 0; kk < 16; kk += 8) {
            wmma::fragment<wmma::matrix_a, 16, 16, 8, wmma::precision::tf32, wmma::row_major> a[2];
            wmma::fragment<wmma::matrix_b, 16, 16, 8, wmma::precision::tf32, wmma::row_major> b[4];
#pragma unroll
            for (int i = 0; i < 2; i++) {
                wmma::load_matrix_sync(a[i], &As[warp_m + i * 16][kk], 16);
#pragma unroll
                for (int t = 0; t < a[i].num_elements; t++)
                    a[i].x[t] = wmma::__float_to_tf32(a[i].x[t]);
            }
#pragma unroll
            for (int j = 0; j < 4; j++) {
                wmma::load_matrix_sync(b[j], &Bs[kk][warp_n + j * 16], 136);
#pragma unroll
                for (int t = 0; t < b[j].num_elements; t++)
                    b[j].x[t] = wmma::__float_to_tf32(b[j].x[t]);
            }
#pragma unroll
            for (int i = 0; i < 2; i++)
#pragma unroll
                for (int j = 0; j < 4; j++)
                    wmma::mma_sync(c[i][j], a[i], b[j], c[i][j]);
        }
        __syncthreads();
    }

#pragma unroll
    for (int i = 0; i < 2; i++)
#pragma unroll
        for (int j = 0; j < 4; j++)
            wmma::store_matrix_sync(
                out + (size_t)(block_row0 + warp_m + i * 16) * D + warp_n + j * 16,
                c[i][j], D, wmma::mem_row_major);
}

// Guarded FFMA GEMM for the 80-row tail (rows >= TAIL_ROW0).
__global__ void __launch_bounds__(256) gemm_tail_kernel(const float* __restrict__ x,
                                                        const float* __restrict__ bias,
                                                        float* __restrict__ outp,
                                                        int layer) {
    const float* __restrict__ wt  = (layer == 0) ? d_wt1 : d_wt2;
    const float* __restrict__ xin = (layer == 0) ? x : d_h;
    float* __restrict__ out       = (layer == 0) ? d_h : outp;

    __shared__ float As[16][132];
    __shared__ float Bs[16][128];

    int tid = threadIdx.x;
    int block_row0 = TAIL_ROW0;
    int rowg = (tid >> 4) * 8;
    int colg = (tid & 15) * 8;

    float acc[8][8];
#pragma unroll
    for (int i = 0; i < 8; i++)
#pragma unroll
        for (int j = 0; j < 8; j++) acc[i][j] = 0.0f;

    for (int kt = 0; kt < 256; kt += 16) {
        const float* __restrict__ asrc = (kt < 128) ? d_agg : xin;
        int kbase = (kt < 128) ? kt : (kt - 128);
#pragma unroll
        for (int p = 0; p < 2; p++) {
            int idx = tid + p * 256;
            int r = idx >> 2;
            int kq = (idx & 3) * 4;
            int gr = block_row0 + r;
            int grc = (gr < N_NODES) ? gr : (N_NODES - 1);
            float4 v = *(const float4*)(asrc + (size_t)grc * D + kbase + kq);
            As[kq + 0][r] = v.x;
            As[kq + 1][r] = v.y;
            As[kq + 2][r] = v.z;
            As[kq + 3][r] = v.w;
        }
#pragma unroll
        for (int p = 0; p < 2; p++) {
            int idx = tid + p * 256;
            int k = idx >> 5;
            int j = (idx & 31) * 4;
            *(float4*)&Bs[k][j] = *(const float4*)(wt + (size_t)(kt + k) * 128 + j);
        }
        __syncthreads();

#pragma unroll
        for (int k = 0; k < 16; k++) {
            float4 a0 = *(const float4*)&As[k][rowg];
            float4 a1 = *(const float4*)&As[k][rowg + 4];
            float4 b0 = *(const float4*)&Bs[k][colg];
            float4 b1 = *(const float4*)&Bs[k][colg + 4];
            float a[8] = {a0.x, a0.y, a0.z, a0.w, a1.x, a1.y, a1.z, a1.w};
            float b[8] = {b0.x, b0.y, b0.z, b0.w, b1.x, b1.y, b1.z, b1.w};
#pragma unroll
            for (int i = 0; i < 8; i++)
#pragma unroll
                for (int j = 0; j < 8; j++)
                    acc[i][j] += a[i] * b[j];
        }
        __syncthreads();
    }

    float bb[8];
#pragma unroll
    for (int j = 0; j < 8; j++) bb[j] = __ldg(bias + colg + j);
#pragma unroll
    for (int i = 0; i < 8; i++) {
        int gr = block_row0 + rowg + i;
        if (gr < N_NODES) {
            float4 o0, o1;
            o0.x = acc[i][0] + bb[0]; o0.y = acc[i][1] + bb[1];
            o0.z = acc[i][2] + bb[2]; o0.w = acc[i][3] + bb[3];
            o1.x = acc[i][4] + bb[4]; o1.y = acc[i][5] + bb[5];
            o1.z = acc[i][6] + bb[6]; o1.w = acc[i][7] + bb[7];
            *(float4*)(out + (size_t)gr * D + colg)     = o0;
            *(float4*)(out + (size_t)gr * D + colg + 4) = o1;
        }
    }
}

// ---------------------------------------------------------------------------
extern "C" void kernel_launch(void* const* d_in, const int* in_sizes, int n_in,
                              void* d_out, int out_size) {
    const float* x   = (const float*)d_in[0];
    const int*   ei  = (const int*)d_in[1];
    const float* Wl1 = (const float*)d_in[2];
    const float* bl1 = (const float*)d_in[3];
    const float* Wr1 = (const float*)d_in[4];
    const float* Wl2 = (const float*)d_in[5];
    const float* bl2 = (const float*)d_in[6];
    const float* Wr2 = (const float*)d_in[7];
    float* out = (float*)d_out;

    const int* src = ei;
    const int* dst = ei + E_EDGES;

    const int gather_blocks = (N_NODES * 32 + 255) / 256;

    // ---- CSR build (shared across both layers) ----
    zero_deg_kernel<<<(N_NODES + 255) / 256, 256>>>();
    count_kernel<<<(E_EDGES + 511) / 512, 256>>>(dst);
    scan1_kernel<<<SCAN_NB, SCAN_BLK>>>();
    scan2_kernel<<<1, 64>>>();
    scan3_kernel<<<(N_NODES + 255) / 256, 256>>>();
    fill_kernel<<<(E_EDGES + 511) / 512, 256>>>(src, dst);
    prep_kernel<<<128, 256>>>(Wl1, Wr1, Wl2, Wr2);

    // ---- layer 1 ----
    gather_kernel<<<gather_blocks, 256>>>(x, 0);
    gemm_tf32_kernel<<<FULL_TILES, 256>>>(x, bl1, nullptr, 0);
    gemm_tail_kernel<<<1, 256>>>(x, bl1, nullptr, 0);

    // ---- layer 2 ----
    gather_kernel<<<gather_blocks, 256>>>(x, 1);
    gemm_tf32_kernel<<<FULL_TILES, 256>>>(x, bl2, out, 1);
    gemm_tail_kernel<<<1, 256>>>(x, bl2, out, 1);
}

// round 7
// speedup vs baseline: 1.0255x; 1.0255x over previous
#include <cuda_runtime.h>
#include <cstddef>

#define N_NODES 50000
#define D 128
#define E_EDGES 800000
#define SCAN_BLK 1024
#define SCAN_NB ((N_NODES + SCAN_BLK - 1) / SCAN_BLK)   // 49

// Scratch (no allocations allowed in kernel_launch)
__device__ float d_agg[(size_t)N_NODES * D];   // mean-aggregated features
__device__ float d_h[(size_t)N_NODES * D];     // layer-1 output
__device__ int   d_deg[N_NODES];
__device__ int   d_rowptr[N_NODES + 1];
__device__ int   d_cursor[N_NODES + 1];
__device__ int   d_adj[E_EDGES];               // src ids grouped by dst
__device__ int   d_bsum[64];
__device__ int   d_boff[64];
__device__ float d_wt1[256 * 128];             // combined [Wl1;Wr1] transposed: wt[k][j]
__device__ float d_wt2[256 * 128];

// ---------------------------------------------------------------------------
__global__ void zero_deg_kernel() {
    int i = blockIdx.x * blockDim.x + threadIdx.x;
    if (i < N_NODES) d_deg[i] = 0;
}

__global__ void count_kernel(const int* __restrict__ dst) {
    int stride = gridDim.x * blockDim.x;
    for (int e = blockIdx.x * blockDim.x + threadIdx.x; e < E_EDGES; e += stride) {
        atomicAdd(&d_deg[dst[e]], 1);
    }
}

// intra-block inclusive scan (warp-shuffle based) -> rowptr[i+1]; block sums -> d_bsum
__global__ void scan1_kernel() {
    __shared__ int wsum[32];
    int i = blockIdx.x * SCAN_BLK + threadIdx.x;
    int lane = threadIdx.x & 31;
    int warp = threadIdx.x >> 5;
    int v = (i < N_NODES) ? d_deg[i] : 0;
    int s = v;
#pragma unroll
    for (int off = 1; off < 32; off <<= 1) {
        int t = __shfl_up_sync(0xffffffffu, s, off);
        if (lane >= off) s += t;
    }
    if (lane == 31) wsum[warp] = s;
    __syncthreads();
    if (warp == 0) {
        int w = wsum[lane];
#pragma unroll
        for (int off = 1; off < 32; off <<= 1) {
            int t = __shfl_up_sync(0xffffffffu, w, off);
            if (lane >= off) w += t;
        }
        wsum[lane] = w;
    }
    __syncthreads();
    int incl = s + (warp > 0 ? wsum[warp - 1] : 0);
    if (i < N_NODES) d_rowptr[i + 1] = incl;
    if (threadIdx.x == SCAN_BLK - 1) d_bsum[blockIdx.x] = incl;
}

// exclusive scan of the 49 block sums (single block, 64 threads)
__global__ void scan2_kernel() {
    __shared__ int sh[64];
    int t = threadIdx.x;
    int v = (t < SCAN_NB) ? d_bsum[t] : 0;
    sh[t] = v;
    __syncthreads();
#pragma unroll
    for (int off = 1; off < 64; off <<= 1) {
        int u = (t >= off) ? sh[t - off] : 0;
        __syncthreads();
        sh[t] += u;
        __syncthreads();
    }
    d_boff[t] = sh[t] - v;   // exclusive
}

// finalize rowptr and seed fill cursors
__global__ void scan3_kernel() {
    int i = blockIdx.x * blockDim.x + threadIdx.x;
    if (i == 0) { d_rowptr[0] = 0; d_cursor[0] = 0; }
    if (i < N_NODES) {
        int r = d_rowptr[i + 1] + d_boff[i >> 10];
        d_rowptr[i + 1] = r;
        d_cursor[i + 1] = r;
    }
}

__global__ void fill_kernel(const int* __restrict__ src, const int* __restrict__ dst) {
    int stride = gridDim.x * blockDim.x;
    for (int e = blockIdx.x * blockDim.x + threadIdx.x; e < E_EDGES; e += stride) {
        int d = dst[e];
        int p = atomicAdd(&d_cursor[d], 1);
        d_adj[p] = src[e];
    }
}

// wt[k*128+j]: k<128 -> Wl[j][k]; k>=128 -> Wr[j][k-128]
__global__ void prep_kernel(const float* __restrict__ Wl1, const float* __restrict__ Wr1,
                            const float* __restrict__ Wl2, const float* __restrict__ Wr2) {
    int stride = gridDim.x * blockDim.x;
    for (int i = blockIdx.x * blockDim.x + threadIdx.x; i < 256 * 128; i += stride) {
        int k = i >> 7;
        int j = i & 127;
        if (k < 128) {
            d_wt1[i] = Wl1[j * 128 + k];
            d_wt2[i] = Wl2[j * 128 + k];
        } else {
            d_wt1[i] = Wr1[j * 128 + (k - 128)];
            d_wt2[i] = Wr2[j * 128 + (k - 128)];
        }
    }
}

// One warp per node: sum neighbor rows, scale by 1/deg, store.
// 4-wide unroll keeps 4 independent L2 loads in flight per lane.
__global__ void __launch_bounds__(256) gather_kernel(const float* __restrict__ x, int layer) {
    const float* __restrict__ xin = (layer == 0) ? x : d_h;
    int gid = blockIdx.x * blockDim.x + threadIdx.x;
    int n = gid >> 5;
    if (n >= N_NODES) return;
    int lane = gid & 31;
    int base = d_rowptr[n];
    int end  = d_rowptr[n + 1];
    int deg  = end - base;
    size_t feat = (size_t)lane * 4;

    float4 acc = make_float4(0.f, 0.f, 0.f, 0.f);
    for (int i = base; i < end; i += 32) {
        int cnt = min(32, end - i);
        int sidx = (lane < cnt) ? __ldg(d_adj + i + lane) : 0;
        int j = 0;
        for (; j + 4 <= cnt; j += 4) {
            int s0 = __shfl_sync(0xffffffffu, sidx, j);
            int s1 = __shfl_sync(0xffffffffu, sidx, j + 1);
            int s2 = __shfl_sync(0xffffffffu, sidx, j + 2);
            int s3 = __shfl_sync(0xffffffffu, sidx, j + 3);
            float4 v0 = *(const float4*)(xin + (size_t)s0 * D + feat);
            float4 v1 = *(const float4*)(xin + (size_t)s1 * D + feat);
            float4 v2 = *(const float4*)(xin + (size_t)s2 * D + feat);
            float4 v3 = *(const float4*)(xin + (size_t)s3 * D + feat);
            float px = (v0.x + v1.x) + (v2.x + v3.x);
            float py = (v0.y + v1.y) + (v2.y + v3.y);
            float pz = (v0.z + v1.z) + (v2.z + v3.z);
            float pw = (v0.w + v1.w) + (v2.w + v3.w);
            acc.x += px; acc.y += py; acc.z += pz; acc.w += pw;
        }
        for (; j < cnt; j++) {
            int s = __shfl_sync(0xffffffffu, sidx, j);
            float4 v = *(const float4*)(xin + (size_t)s * D + feat);
            acc.x += v.x; acc.y += v.y; acc.z += v.z; acc.w += v.w;
        }
    }
    float sc = 1.0f / fmaxf((float)deg, 1.0f);
    acc.x *= sc; acc.y *= sc; acc.z *= sc; acc.w *= sc;
    *(float4*)(d_agg + (size_t)n * D + feat) = acc;
}

// Fused: out[n][j] = sum_{k<128} agg[n][k]*wt[k][j] + sum_{k>=128} xin[n][k-128]*wt[k][j] + b[j]
// SGEMM: BM=128, BN=128, BK=16, 256 threads, 8x8 microtile, double-buffered shared.
__global__ void __launch_bounds__(256) gemm_kernel(const float* __restrict__ x,
                                                   const float* __restrict__ bias,
                                                   float* __restrict__ outp,
                                                   int layer) {
    const float* __restrict__ wt  = (layer == 0) ? d_wt1 : d_wt2;
    const float* __restrict__ xin = (layer == 0) ? x : d_h;
    float* __restrict__ out       = (layer == 0) ? d_h : outp;

    __shared__ float As[2][16][132];   // [buf][k][m]
    __shared__ float Bs[2][16][128];   // [buf][k][j]

    int tid = threadIdx.x;
    int block_row0 = blockIdx.x * 128;
    int rowg = (tid >> 4) * 8;
    int colg = (tid & 15) * 8;

    float acc[8][8];
#pragma unroll
    for (int i = 0; i < 8; i++)
#pragma unroll
        for (int j = 0; j < 8; j++) acc[i][j] = 0.0f;

    float4 va[2], vb[2];

    // ---- prefetch tile 0 into registers ----
#pragma unroll
    for (int p = 0; p < 2; p++) {
        int idx = tid + p * 256;
        int r = idx >> 2;
        int kq = (idx & 3) * 4;
        int gr = block_row0 + r;
        int grc = (gr < N_NODES) ? gr : (N_NODES - 1);
        va[p] = *(const float4*)(d_agg + (size_t)grc * D + 0 + kq);
        int k = idx >> 5;
        int j = (idx & 31) * 4;
        vb[p] = *(const float4*)(wt + (size_t)(0 + k) * 128 + j);
    }
    // store tile 0
#pragma unroll
    for (int p = 0; p < 2; p++) {
        int idx = tid + p * 256;
        int r = idx >> 2;
        int kq = (idx & 3) * 4;
        As[0][kq + 0][r] = va[p].x;
        As[0][kq + 1][r] = va[p].y;
        As[0][kq + 2][r] = va[p].z;
        As[0][kq + 3][r] = va[p].w;
        int k = idx >> 5;
        int j = (idx & 31) * 4;
        *(float4*)&Bs[0][k][j] = vb[p];
    }
    __syncthreads();

#pragma unroll
    for (int t = 0; t < 16; t++) {
        int buf = t & 1;
        // prefetch tile t+1
        if (t < 15) {
            int kt = (t + 1) * 16;
            const float* __restrict__ asrc = (kt < 128) ? d_agg : xin;
            int kbase = (kt < 128) ? kt : (kt - 128);
#pragma unroll
            for (int p = 0; p < 2; p++) {
                int idx = tid + p * 256;
                int r = idx >> 2;
                int kq = (idx & 3) * 4;
                int gr = block_row0 + r;
                int grc = (gr < N_NODES) ? gr : (N_NODES - 1);
                va[p] = *(const float4*)(asrc + (size_t)grc * D + kbase + kq);
                int k = idx >> 5;
                int j = (idx & 31) * 4;
                vb[p] = *(const float4*)(wt + (size_t)(kt + k) * 128 + j);
            }
        }
        // compute on current buffer
#pragma unroll
        for (int k = 0; k < 16; k++) {
            float4 a0 = *(const float4*)&As[buf][k][rowg];
            float4 a1 = *(const float4*)&As[buf][k][rowg + 4];
            float4 b0 = *(const float4*)&Bs[buf][k][colg];
            float4 b1 = *(const float4*)&Bs[buf][k][colg + 4];
            float a[8] = {a0.x, a0.y, a0.z, a0.w, a1.x, a1.y, a1.z, a1.w};
            float b[8] = {b0.x, b0.y, b0.z, b0.w, b1.x, b1.y, b1.z, b1.w};
#pragma unroll
            for (int i = 0; i < 8; i++)
#pragma unroll
                for (int j = 0; j < 8; j++)
                    acc[i][j] += a[i] * b[j];
        }
        // store prefetched tile into other buffer
        if (t < 15) {
#pragma unroll
            for (int p = 0; p < 2; p++) {
                int idx = tid + p * 256;
                int r = idx >> 2;
                int kq = (idx & 3) * 4;
                As[buf ^ 1][kq + 0][r] = va[p].x;
                As[buf ^ 1][kq + 1][r] = va[p].y;
                As[buf ^ 1][kq + 2][r] = va[p].z;
                As[buf ^ 1][kq + 3][r] = va[p].w;
                int k = idx >> 5;
                int j = (idx & 31) * 4;
                *(float4*)&Bs[buf ^ 1][k][j] = vb[p];
            }
        }
        __syncthreads();
    }

    // ---- epilogue: add bias, store ----
    float bb[8];
#pragma unroll
    for (int j = 0; j < 8; j++) bb[j] = __ldg(bias + colg + j);
#pragma unroll
    for (int i = 0; i < 8; i++) {
        int gr = block_row0 + rowg + i;
        if (gr < N_NODES) {
            float4 o0, o1;
            o0.x = acc[i][0] + bb[0]; o0.y = acc[i][1] + bb[1];
            o0.z = acc[i][2] + bb[2]; o0.w = acc[i][3] + bb[3];
            o1.x = acc[i][4] + bb[4]; o1.y = acc[i][5] + bb[5];
            o1.z = acc[i][6] + bb[6]; o1.w = acc[i][7] + bb[7];
            *(float4*)(out + (size_t)gr * D + colg)     = o0;
            *(float4*)(out + (size_t)gr * D + colg + 4) = o1;
        }
    }
}

// ---------------------------------------------------------------------------
extern "C" void kernel_launch(void* const* d_in, const int* in_sizes, int n_in,
                              void* d_out, int out_size) {
    const float* x   = (const float*)d_in[0];
    const int*   ei  = (const int*)d_in[1];
    const float* Wl1 = (const float*)d_in[2];
    const float* bl1 = (const float*)d_in[3];
    const float* Wr1 = (const float*)d_in[4];
    const float* Wl2 = (const float*)d_in[5];
    const float* bl2 = (const float*)d_in[6];
    const float* Wr2 = (const float*)d_in[7];
    float* out = (float*)d_out;

    const int* src = ei;
    const int* dst = ei + E_EDGES;

    const int gather_blocks = (N_NODES * 32 + 255) / 256;
    const int gemm_blocks   = (N_NODES + 127) / 128;

    // ---- CSR build (shared across both layers) ----
    zero_deg_kernel<<<(N_NODES + 255) / 256, 256>>>();
    count_kernel<<<(E_EDGES + 511) / 512, 256>>>(dst);
    scan1_kernel<<<SCAN_NB, SCAN_BLK>>>();
    scan2_kernel<<<1, 64>>>();
    scan3_kernel<<<(N_NODES + 255) / 256, 256>>>();
    fill_kernel<<<(E_EDGES + 511) / 512, 256>>>(src, dst);
    prep_kernel<<<128, 256>>>(Wl1, Wr1, Wl2, Wr2);

    // ---- layer 1 ----
    gather_kernel<<<gather_blocks, 256>>>(x, 0);
    gemm_kernel<<<gemm_blocks, 256>>>(x, bl1, nullptr, 0);

    // ---- layer 2 ----
    gather_kernel<<<gather_blocks, 256>>>(x, 1);
    gemm_kernel<<<gemm_blocks, 256>>>(x, bl2, out, 1);
}